// round 16
// baseline (speedup 1.0000x reference)
#include <cuda_runtime.h>
#include <cuda_fp16.h>

// preds [B=8, N=16, C=4, H=128, W=256] f32, gt [8,4,128,256] f32, out scalar f32
#define CHW     131072
#define NCHW    (16 * CHW)
#define NPIX    1048576
#define NBLK    1024
#define NTHR    256        // 262144 threads; each handles 2 float2 pixel-pairs
                           // (batch b and batch b+4), 4 px total

__device__ float        g_partials[NBLK];
__device__ unsigned int g_done = 0;

__device__ __forceinline__ void cash(__half2 &a, __half2 &b) {
    const __half2 lo = __hmin2(a, b);
    const __half2 hi = __hmax2(a, b);
    a = lo; b = hi;
}
// Pipe-split cas: min on alu, max = (a+b)-min on fma (exact multiset up to one
// unbiased f16 rounding; used only in the final network layers)
__device__ __forceinline__ void cashx(__half2 &a, __half2 &b) {
    const __half2 s  = __hadd2(a, b);
    const __half2 lo = __hmin2(a, b);
    b = __hsub2(s, lo);
    a = lo;
}

// Green's 16-input 60-comparator network; last 21 comparators pipe-split
__device__ __forceinline__ void sort16h(__half2 v[16]) {
    cash(v[0],v[1]);  cash(v[2],v[3]);  cash(v[4],v[5]);  cash(v[6],v[7]);
    cash(v[8],v[9]);  cash(v[10],v[11]);cash(v[12],v[13]);cash(v[14],v[15]);
    cash(v[0],v[2]);  cash(v[4],v[6]);  cash(v[8],v[10]); cash(v[12],v[14]);
    cash(v[1],v[3]);  cash(v[5],v[7]);  cash(v[9],v[11]); cash(v[13],v[15]);
    cash(v[0],v[4]);  cash(v[8],v[12]); cash(v[1],v[5]);  cash(v[9],v[13]);
    cash(v[2],v[6]);  cash(v[10],v[14]);cash(v[3],v[7]);  cash(v[11],v[15]);
    cash(v[0],v[8]);  cash(v[1],v[9]);  cash(v[2],v[10]); cash(v[3],v[11]);
    cash(v[4],v[12]); cash(v[5],v[13]); cash(v[6],v[14]); cash(v[7],v[15]);
    cash(v[5],v[10]); cash(v[6],v[9]);  cash(v[3],v[12]); cash(v[13],v[14]);
    cash(v[7],v[11]); cash(v[1],v[2]);  cash(v[4],v[8]);
    cashx(v[1],v[4]); cashx(v[7],v[13]);cashx(v[2],v[8]); cashx(v[11],v[14]);
    cashx(v[5],v[6]); cashx(v[9],v[10]);
    cashx(v[2],v[4]); cashx(v[11],v[13]);cashx(v[3],v[8]);cashx(v[7],v[12]);
    cashx(v[6],v[8]); cashx(v[10],v[12]);cashx(v[3],v[5]);cashx(v[7],v[9]);
    cashx(v[3],v[4]); cashx(v[5],v[6]); cashx(v[7],v[8]); cashx(v[9],v[10]);
    cashx(v[11],v[12]);
    cashx(v[6],v[7]); cashx(v[8],v[9]);
}

// Full per-pixel-pair CRPS contribution from f32 staging (term1 f16 + sort + term2)
__device__ __forceinline__ float tile_crps(const float2 v[16], const float2 g) {
    const __half2 gh = __floats2half2_rn(g.x, g.y);
    __half2 h[16];
    #pragma unroll
    for (int n = 0; n < 16; n++) h[n] = __floats2half2_rn(v[n].x, v[n].y);

    __half2 s0 = __float2half2_rn(0.f), s1 = s0;
    #pragma unroll
    for (int n = 0; n < 16; n += 2) {
        s0 = __hadd2(s0, __habs2(__hsub2(h[n],     gh)));
        s1 = __hadd2(s1, __habs2(__hsub2(h[n + 1], gh)));
    }
    const float2 f1 = __half22float2(__hadd2(s0, s1));

    sort16h(h);

    float2 t2 = make_float2(0.f, 0.f);
    #pragma unroll
    for (int k = 0; k < 8; k++) {
        const float w = (float)(2 * k - 15);
        const float2 d = __half22float2(__hsub2(h[k], h[15 - k]));
        t2.x = fmaf(w, d.x, t2.x);
        t2.y = fmaf(w, d.y, t2.y);
    }

    const float c1 = 1.0f / (16.0f * (float)NPIX);
    const float c2 = 1.0f / (240.0f * (float)NPIX);     // N*(N-1) = 240
    return (f1.x + f1.y) * c1 - (t2.x + t2.y) * c2;
}

__global__ __launch_bounds__(NTHR, 2) void crps_main(const float* __restrict__ preds,
                                                     const float* __restrict__ gt,
                                                     float* __restrict__ out) {
    const int t    = blockIdx.x * NTHR + threadIdx.x;   // 0 .. 262143
    const int b    = t >> 16;                           // batch 0..3 (pair: b, b+4)
    const int off2 = t & 65535;                         // float2 index within [C,H,W]

    const float2* pA = reinterpret_cast<const float2*>(preds) + ((b * NCHW) >> 1) + off2;
    const float2* pB = pA + ((4 * NCHW) >> 1);

    // 34 front-batched independent LDG.64: double the per-thread MLP
    float2 vA[16], vB[16];
    #pragma unroll
    for (int n = 0; n < 16; n++) vA[n] = __ldcg(pA + ((n * CHW) >> 1));
    #pragma unroll
    for (int n = 0; n < 16; n++) vB[n] = __ldcg(pB + ((n * CHW) >> 1));
    const float2 gA = __ldcg(reinterpret_cast<const float2*>(gt) + ((b * CHW) >> 1) + off2);
    const float2 gB = __ldcg(reinterpret_cast<const float2*>(gt) + (((b + 4) * CHW) >> 1) + off2);

    // Tile A computes while tile B's loads are still in flight
    float val = tile_crps(vA, gA);
    val      += tile_crps(vB, gB);

    // Deterministic block reduction (8 warps)
    #pragma unroll
    for (int o = 16; o > 0; o >>= 1) val += __shfl_down_sync(0xffffffffu, val, o);
    __shared__ float s[NTHR / 32];
    if ((threadIdx.x & 31) == 0) s[threadIdx.x >> 5] = val;
    __syncthreads();
    if (threadIdx.x < 32) {
        float x = (threadIdx.x < (NTHR / 32)) ? s[threadIdx.x] : 0.f;
        #pragma unroll
        for (int o = 4; o > 0; o >>= 1) x += __shfl_down_sync(0xffu, x, o);
        if (threadIdx.x == 0) g_partials[blockIdx.x] = x;
    }

    // Fused last-block final reduction (deterministic order; atomic only elects)
    __shared__ bool s_last;
    __threadfence();
    if (threadIdx.x == 0) {
        unsigned int r = atomicAdd(&g_done, 1u);
        s_last = (r == (unsigned)(NBLK - 1));
    }
    __syncthreads();
    if (s_last) {
        const int tid = threadIdx.x;
        float acc = 0.f;
        #pragma unroll
        for (int i = 0; i < NBLK / NTHR; i++)          // 4 reads, fixed order
            acc += __ldcg(&g_partials[tid + i * NTHR]);
        #pragma unroll
        for (int o = 16; o > 0; o >>= 1) acc += __shfl_down_sync(0xffffffffu, acc, o);
        __shared__ float s2[NTHR / 32];
        if ((tid & 31) == 0) s2[tid >> 5] = acc;
        __syncthreads();
        if (tid == 0) {
            out[0] = s2[0] + s2[1] + s2[2] + s2[3]
                   + s2[4] + s2[5] + s2[6] + s2[7];
            g_done = 0;                                // reset for next graph replay
        }
    }
}

extern "C" void kernel_launch(void* const* d_in, const int* in_sizes, int n_in,
                              void* d_out, int out_size) {
    const float* preds = (const float*)d_in[0];  // [8,16,4,128,256]
    const float* gt    = (const float*)d_in[1];  // [8,4,128,256]
    float* out = (float*)d_out;                  // scalar f32
    (void)in_sizes; (void)n_in; (void)out_size;
    crps_main<<<NBLK, NTHR>>>(preds, gt, out);
}